// round 9
// baseline (speedup 1.0000x reference)
#include <cuda_runtime.h>
#include <math_constants.h>

// Shapes fixed by setup_inputs: N=8192, K=16
#define NQ     8192
#define KTOP   16
#define NSEG   64                // filter sub-slices
#define SSLEN  128               // candidates per sub-slice (NSEG*SSLEN = NQ)
#define SEG    16                // per-(query,subslice) admitted cap (mean ~0.67)
#define NGRP   8                 // threshold groups (top-2 each -> >=16 admits)
#define NSUB   4                 // sub-partials per group
#define GSUB   96                // candidates per sub-partial (8*4*96 = 3072)
#define FB     128               // threads per block
#define QPT    4                 // queries per thread (gmax/filter)
#define NRB    512               // reduce blocks

// Static scratch (no runtime allocation allowed)
__device__ float4 g_cand[NQ];                  // (cx, cy, -0.5|c|^2, 0) for reduce
__device__ float2 g_gmax2[NGRP * NSUB][NQ];    // per-(group,sub) top-2 of s
__device__ float2 g_pair[NQ * NSEG * SEG];     // admitted (s, idx-bits)
__device__ int    g_cnt[NQ][NSEG];             // per-(query,subslice) counts
__device__ int    g_idx[NQ * KTOP];            // top-16 indices, query-major
__device__ float  g_part[NRB];                 // partial sums

// score: s = x.c - 0.5|c|^2  (dist = |x|^2 - 2s; larger s == closer).
// Explicit FMA chain -> bitwise identical in gmax and filter.
__device__ __forceinline__ float s_of(float cx, float cy, float nh,
                                      float x1, float x2)
{
    return __fmaf_rn(x2, cy, __fmaf_rn(x1, cx, nh));
}

// candidate prep: poly(ch2[i]) and -0.5*|.|^2, explicit FMA chain so every
// kernel computing it inline produces identical bits.
__device__ __forceinline__ float4 poly4(const float2* __restrict__ ch2,
                                        const float* __restrict__ M1,
                                        const float* __restrict__ M2, int i)
{
    float2 a = ch2[i];
    float p  = __fmul_rn(a.x, a.y);
    float y1 = __fmaf_rn(M1[1], a.y, __fmaf_rn(M1[2], a.x, __fmaf_rn(M1[3], p, M1[0])));
    float y2 = __fmaf_rn(M2[1], a.y, __fmaf_rn(M2[2], a.x, __fmaf_rn(M2[3], p, M2[0])));
    float nh = -0.5f * __fmaf_rn(y1, y1, __fmul_rn(y2, y2));
    return make_float4(y1, y2, nh, 0.0f);
}

// order-preserving float->uint key (monotone)
__device__ __forceinline__ unsigned fkey(float f)
{
    unsigned u = __float_as_uint(f);
    return u ^ ((unsigned)((int)u >> 31) | 0x80000000u);
}

// ---------------------------------------------------------------------------
// Kernel 1: gmax. Block = (512 queries via 4/thread, sub-partial y).
// y = g*4+sub covers candidates [y*96, y*96+96). Branch-free top-2 per query.
// y==0 blocks additionally write g_cand (prep fused; used only by reduce).
// ---------------------------------------------------------------------------
__global__ __launch_bounds__(FB)
void gmax_kernel(const float2* __restrict__ ch1, const float2* __restrict__ ch2,
                 const float* __restrict__ M1, const float* __restrict__ M2)
{
    __shared__ float4 sc[GSUB];

    const int tid = threadIdx.x;
    const int y   = blockIdx.y;
    const int qb  = blockIdx.x * (FB * QPT);

    if (tid < GSUB)
        sc[tid] = poly4(ch2, M1, M2, y * GSUB + tid);

    if (y == 0) {   // fused prep for reduce's gather table
#pragma unroll
        for (int h = 0; h < QPT; ++h) {
            int i0 = qb + h * FB + tid;
            g_cand[i0] = poly4(ch2, M1, M2, i0);
        }
    }
    __syncthreads();

    const int q0 = qb + tid;
    const float2 xa = ch1[q0];
    const float2 xb = ch1[q0 + FB];
    const float2 xc = ch1[q0 + 2 * FB];
    const float2 xd = ch1[q0 + 3 * FB];

    float m1a = -CUDART_INF_F, m2a = -CUDART_INF_F;
    float m1b = -CUDART_INF_F, m2b = -CUDART_INF_F;
    float m1c = -CUDART_INF_F, m2c = -CUDART_INF_F;
    float m1d = -CUDART_INF_F, m2d = -CUDART_INF_F;
#pragma unroll 8
    for (int t = 0; t < GSUB; ++t) {
        float4 c = sc[t];
        float sa = s_of(c.x, c.y, c.z, xa.x, xa.y);
        float sb = s_of(c.x, c.y, c.z, xb.x, xb.y);
        float scc = s_of(c.x, c.y, c.z, xc.x, xc.y);
        float sd = s_of(c.x, c.y, c.z, xd.x, xd.y);
        m2a = fmaxf(m2a, fminf(m1a, sa));  m1a = fmaxf(m1a, sa);
        m2b = fmaxf(m2b, fminf(m1b, sb));  m1b = fmaxf(m1b, sb);
        m2c = fmaxf(m2c, fminf(m1c, scc)); m1c = fmaxf(m1c, scc);
        m2d = fmaxf(m2d, fminf(m1d, sd));  m1d = fmaxf(m1d, sd);
    }
    g_gmax2[y][q0]          = make_float2(m1a, m2a);
    g_gmax2[y][q0 + FB]     = make_float2(m1b, m2b);
    g_gmax2[y][q0 + 2 * FB] = make_float2(m1c, m2c);
    g_gmax2[y][q0 + 3 * FB] = make_float2(m1d, m2d);
}

// exact top-2 merge of 4 sub-partials per group; T = min over groups of m2.
// Guarantee: every group's true top-2 have s >= m2 >= T  ->  >=16 admits.
__device__ __forceinline__ float tmin_of(int j)
{
    float T = CUDART_INF_F;
#pragma unroll
    for (int g = 0; g < NGRP; ++g) {
        float m1 = -CUDART_INF_F, m2 = -CUDART_INF_F;
#pragma unroll
        for (int sb = 0; sb < NSUB; ++sb) {
            float2 p = g_gmax2[g * NSUB + sb][j];
            m2 = fmaxf(fmaxf(m2, p.y), fminf(m1, p.x));
            m1 = fmaxf(m1, p.x);
        }
        T = fminf(T, m2);
    }
    return T;
}

// ---------------------------------------------------------------------------
// Kernel 2: filter (+tmin fused). Block = (512 queries via 4/thread,
// sub-slice sl of 128 candidates). Appends (s, idx) with s >= T to private
// segments; register counters -> deterministic, ascending-index (stable).
// ---------------------------------------------------------------------------
__global__ __launch_bounds__(FB)
void filter_kernel(const float2* __restrict__ ch1, const float2* __restrict__ ch2,
                   const float* __restrict__ M1, const float* __restrict__ M2)
{
    __shared__ float4 sc[SSLEN];   // 2 KB

    const int tid = threadIdx.x;
    const int sl  = blockIdx.y;
    const int qb  = blockIdx.x * (FB * QPT);

    if (tid < SSLEN)
        sc[tid] = poly4(ch2, M1, M2, sl * SSLEN + tid);
    __syncthreads();

    const int q0 = qb + tid;
    const int q1 = q0 + FB, q2 = q0 + 2 * FB, q3 = q0 + 3 * FB;
    const float T0 = tmin_of(q0), T1 = tmin_of(q1);
    const float T2 = tmin_of(q2), T3 = tmin_of(q3);
    const float2 xa = ch1[q0];
    const float2 xb = ch1[q1];
    const float2 xc = ch1[q2];
    const float2 xd = ch1[q3];
    float2* p0 = &g_pair[(q0 * NSEG + sl) * SEG];
    float2* p1 = &g_pair[(q1 * NSEG + sl) * SEG];
    float2* p2 = &g_pair[(q2 * NSEG + sl) * SEG];
    float2* p3 = &g_pair[(q3 * NSEG + sl) * SEG];

    int c0 = 0, c1 = 0, c2 = 0, c3 = 0;
#pragma unroll 8
    for (int t = 0; t < SSLEN; ++t) {
        float4 c = sc[t];
        float s0 = s_of(c.x, c.y, c.z, xa.x, xa.y);
        float s1 = s_of(c.x, c.y, c.z, xb.x, xb.y);
        float s2 = s_of(c.x, c.y, c.z, xc.x, xc.y);
        float s3 = s_of(c.x, c.y, c.z, xd.x, xd.y);
        float fi = __int_as_float(sl * SSLEN + t);
        if (s0 >= T0) { p0[c0 & (SEG - 1)] = make_float2(s0, fi); ++c0; }
        if (s1 >= T1) { p1[c1 & (SEG - 1)] = make_float2(s1, fi); ++c1; }
        if (s2 >= T2) { p2[c2 & (SEG - 1)] = make_float2(s2, fi); ++c2; }
        if (s3 >= T3) { p3[c3 & (SEG - 1)] = make_float2(s3, fi); ++c3; }
    }
    g_cnt[q0][sl] = min(c0, SEG);
    g_cnt[q1][sl] = min(c1, SEG);
    g_cnt[q2][sl] = min(c2, SEG);
    g_cnt[q3][sl] = min(c3, SEG);
}

// ---------------------------------------------------------------------------
// Kernel 3 (R7-validated shape): stable top-16, one warp per query.
// Lane l owns segments 2l, 2l+1 (scanned in ascending index order -> stable).
// 16 rounds of redux-max(key) + redux-min(idx) == (s desc, idx asc)
// == lax.top_k order.
// ---------------------------------------------------------------------------
__global__ __launch_bounds__(FB)
void select_kernel()
{
    const int j    = (blockIdx.x * FB + threadIdx.x) >> 5;  // query
    const int lane = threadIdx.x & 31;

    float l[KTOP];
    int   li[KTOP];
#pragma unroll
    for (int m = 0; m < KTOP; ++m) { l[m] = -CUDART_INF_F; li[m] = 0x7fffffff; }

#pragma unroll
    for (int h = 0; h < 2; ++h) {
        const int slseg = 2 * lane + h;
        const int cn = g_cnt[j][slseg];
        const float2* sp = &g_pair[(j * NSEG + slseg) * SEG];
        for (int c = 0; c < cn; ++c) {
            float2 pr = sp[c];
            float s  = pr.x;
            int   ci = __float_as_int(pr.y);
            if (s > l[KTOP - 1]) {
#pragma unroll
                for (int m = KTOP - 1; m >= 1; --m) {
                    bool up   = s > l[m - 1];
                    bool here = (!up) && (s > l[m]);
                    float nd  = up ? l[m - 1]  : (here ? s  : l[m]);
                    int   ni  = up ? li[m - 1] : (here ? ci : li[m]);
                    l[m] = nd; li[m] = ni;
                }
                if (s > l[0]) { l[0] = s; li[0] = ci; }
            }
        }
    }

    int out[KTOP];
#pragma unroll
    for (int k = 0; k < KTOP; ++k) {
        unsigned key = fkey(l[0]);
        unsigned mx  = __reduce_max_sync(0xffffffffu, key);
        unsigned cnd = (key == mx) ? (unsigned)li[0] : 0xffffffffu;
        unsigned win = __reduce_min_sync(0xffffffffu, cnd);
        out[k] = (int)win;
        bool pop = (key == mx) && ((unsigned)li[0] == win);
#pragma unroll
        for (int m = 0; m < KTOP - 1; ++m) {
            l[m]  = pop ? l[m + 1]  : l[m];
            li[m] = pop ? li[m + 1] : li[m];
        }
        if (pop) { l[KTOP - 1] = -CUDART_INF_F; li[KTOP - 1] = 0x7fffffff; }
    }

    if (lane == 0) {
#pragma unroll
        for (int k = 0; k < KTOP; ++k)
            g_idx[j * KTOP + k] = out[k];
    }
}

// ---------------------------------------------------------------------------
// Kernel 4 (R7-validated): scrambled gather + KL sum + partials.
// flat m = k*N + q -> a = g_idx[m] (flat == idx.reshape(-1)), b = q.
// ---------------------------------------------------------------------------
__global__ __launch_bounds__(256)
void reduce_kernel(const float2* __restrict__ ch1)
{
    const float scale = -0.5f / 2.25f;   // -0.5 / sigma2^2, sigma2 = 1.5
    const int t = threadIdx.x;
    const int q = blockIdx.x * 16 + (t >> 4);
    const int k = t & 15;

    int a = g_idx[k * NQ + q];           // coalesced along q
    float4 c = g_cand[a];
    float2 x = ch1[q];
    float dy1 = x.x - c.x;
    float dy2 = x.y - c.y;
    float e = expf(scale * fmaf(dy2, dy2, dy1 * dy1));

#pragma unroll
    for (int o = 8; o > 0; o >>= 1)
        e += __shfl_xor_sync(0xffffffffu, e, o);

    __shared__ float sq[16];
    if (k == 0) {
        float expD = e * (1.0f / (float)NQ);
        sq[t >> 4] = (expD != 0.0f) ? logf(expD) : 0.0f;
    }
    __syncthreads();

    if (t < 16) {
        float x2 = sq[t];
#pragma unroll
        for (int o = 8; o > 0; o >>= 1)
            x2 += __shfl_xor_sync(0x0000ffffu, x2, o, 16);
        if (t == 0) g_part[blockIdx.x] = x2;
    }
}

// ---------------------------------------------------------------------------
// Kernel 5: deterministic tree-sum of 512 partials, negate, write out.
// ---------------------------------------------------------------------------
__global__ __launch_bounds__(512)
void final_kernel(float* __restrict__ out)
{
    __shared__ float red[512];
    red[threadIdx.x] = g_part[threadIdx.x];
    __syncthreads();
#pragma unroll
    for (int off = 256; off > 0; off >>= 1) {
        if (threadIdx.x < off) red[threadIdx.x] += red[threadIdx.x + off];
        __syncthreads();
    }
    if (threadIdx.x == 0) out[0] = -red[0];
}

// ---------------------------------------------------------------------------
extern "C" void kernel_launch(void* const* d_in, const int* in_sizes, int n_in,
                              void* d_out, int out_size)
{
    const float2* ch1 = (const float2*)d_in[0];
    const float2* ch2 = (const float2*)d_in[1];
    const float*  M1  = (const float*)d_in[2];
    const float*  M2  = (const float*)d_in[3];
    float* out = (float*)d_out;

    dim3 ggrid(NQ / (FB * QPT), NGRP * NSUB);   // (16, 32)
    gmax_kernel<<<ggrid, FB>>>(ch1, ch2, M1, M2);

    dim3 fgrid(NQ / (FB * QPT), NSEG);          // (16, 64)
    filter_kernel<<<fgrid, FB>>>(ch1, ch2, M1, M2);

    select_kernel<<<NQ * 32 / FB, FB>>>();      // 2048 blocks, 1 warp/query

    reduce_kernel<<<NRB, 256>>>(ch1);           // 512 blocks

    final_kernel<<<1, 512>>>(out);
}

// round 10
// speedup vs baseline: 1.1013x; 1.1013x over previous
#include <cuda_runtime.h>
#include <math_constants.h>

// Shapes fixed by setup_inputs: N=8192, K=16
#define NQ     8192
#define KTOP   16
#define NSEG   32                // filter sub-slices
#define SSLEN  256               // candidates per sub-slice
#define SEG    16                // per-(query,subslice) admitted cap (mean ~1.3)
#define NGRP   8                 // threshold groups (top-2 each -> >=16 admits)
#define NSUB   4                 // sub-partials per group
#define GSUB   96                // candidates per sub-partial (8*4*96 = 3072)
#define FB     128               // threads per block
#define QPT    2                 // queries per thread (gmax/filter)
#define NRB    64                // reduce blocks (128 queries each)

// Static scratch (no runtime allocation allowed)
__device__ float4 g_cand[NQ];                  // (cx, cy, -0.5|c|^2, 0) for reduce
__device__ float2 g_gmax2[NGRP * NSUB][NQ];    // per-(group,sub) top-2 of s
__device__ float2 g_pair[NQ * NSEG * SEG];     // admitted (s, idx-bits)
__device__ int    g_cnt[NQ][NSEG];             // per-(query,subslice) counts
__device__ int    g_idx[NQ * KTOP];            // top-16 indices, query-major
__device__ float  g_part[NRB];                 // partial sums

// score: s = x.c - 0.5|c|^2  (dist = |x|^2 - 2s; larger s == closer).
// Explicit FMA chain -> bitwise identical in gmax and filter.
__device__ __forceinline__ float s_of(float cx, float cy, float nh,
                                      float x1, float x2)
{
    return __fmaf_rn(x2, cy, __fmaf_rn(x1, cx, nh));
}

// candidate prep: poly(ch2[i]) and -0.5*|.|^2, explicit FMA chain so every
// kernel computing it inline produces identical bits.
__device__ __forceinline__ float4 poly4(const float2* __restrict__ ch2,
                                        const float* __restrict__ M1,
                                        const float* __restrict__ M2, int i)
{
    float2 a = ch2[i];
    float p  = __fmul_rn(a.x, a.y);
    float y1 = __fmaf_rn(M1[1], a.y, __fmaf_rn(M1[2], a.x, __fmaf_rn(M1[3], p, M1[0])));
    float y2 = __fmaf_rn(M2[1], a.y, __fmaf_rn(M2[2], a.x, __fmaf_rn(M2[3], p, M2[0])));
    float nh = -0.5f * __fmaf_rn(y1, y1, __fmul_rn(y2, y2));
    return make_float4(y1, y2, nh, 0.0f);
}

// order-preserving float->uint key (monotone)
__device__ __forceinline__ unsigned fkey(float f)
{
    unsigned u = __float_as_uint(f);
    return u ^ ((unsigned)((int)u >> 31) | 0x80000000u);
}

// ---------------------------------------------------------------------------
// Kernel 1 (R7-validated): gmax. Block = (256 queries via 2/thread,
// sub-partial y). y = g*4+sub covers candidates [y*96, y*96+96).
// Branch-free top-2 per query. y==0 blocks also write g_cand (fused prep).
// ---------------------------------------------------------------------------
__global__ __launch_bounds__(FB)
void gmax_kernel(const float2* __restrict__ ch1, const float2* __restrict__ ch2,
                 const float* __restrict__ M1, const float* __restrict__ M2)
{
    __shared__ float4 sc[GSUB];

    const int tid = threadIdx.x;
    const int y   = blockIdx.y;
    const int qb  = blockIdx.x * (FB * QPT);

    if (tid < GSUB)
        sc[tid] = poly4(ch2, M1, M2, y * GSUB + tid);

    if (y == 0) {   // fused prep for reduce's gather table
        int i0 = qb + tid;
        g_cand[i0]      = poly4(ch2, M1, M2, i0);
        g_cand[i0 + FB] = poly4(ch2, M1, M2, i0 + FB);
    }
    __syncthreads();

    const int q0 = qb + tid, q1 = q0 + FB;
    const float2 xa = ch1[q0];
    const float2 xb = ch1[q1];

    float m10 = -CUDART_INF_F, m20 = -CUDART_INF_F;
    float m11 = -CUDART_INF_F, m21 = -CUDART_INF_F;
#pragma unroll 8
    for (int t = 0; t < GSUB; ++t) {
        float4 c = sc[t];
        float s0 = s_of(c.x, c.y, c.z, xa.x, xa.y);
        float s1 = s_of(c.x, c.y, c.z, xb.x, xb.y);
        m20 = fmaxf(m20, fminf(m10, s0));  m10 = fmaxf(m10, s0);
        m21 = fmaxf(m21, fminf(m11, s1));  m11 = fmaxf(m11, s1);
    }
    g_gmax2[y][q0] = make_float2(m10, m20);
    g_gmax2[y][q1] = make_float2(m11, m21);
}

// exact top-2 merge of 4 sub-partials per group; T = min over groups of m2.
// Guarantee: every group's true top-2 have s >= m2 >= T  ->  >=16 admits.
__device__ __forceinline__ float tmin_of(int j)
{
    float T = CUDART_INF_F;
#pragma unroll
    for (int g = 0; g < NGRP; ++g) {
        float m1 = -CUDART_INF_F, m2 = -CUDART_INF_F;
#pragma unroll
        for (int sb = 0; sb < NSUB; ++sb) {
            float2 p = g_gmax2[g * NSUB + sb][j];
            m2 = fmaxf(fmaxf(m2, p.y), fminf(m1, p.x));
            m1 = fmaxf(m1, p.x);
        }
        T = fminf(T, m2);
    }
    return T;
}

// ---------------------------------------------------------------------------
// Kernel 2 (R7-validated): filter (+tmin fused). Block = (256 queries via
// 2/thread, sub-slice sl). Appends (s, idx) with s >= T to private segments;
// register counters -> deterministic, ascending-index order (stable).
// ---------------------------------------------------------------------------
__global__ __launch_bounds__(FB)
void filter_kernel(const float2* __restrict__ ch1, const float2* __restrict__ ch2,
                   const float* __restrict__ M1, const float* __restrict__ M2)
{
    __shared__ float4 sc[SSLEN];   // 4 KB

    const int tid = threadIdx.x;
    const int sl  = blockIdx.y;
    const int qb  = blockIdx.x * (FB * QPT);

    sc[tid]      = poly4(ch2, M1, M2, sl * SSLEN + tid);
    sc[tid + FB] = poly4(ch2, M1, M2, sl * SSLEN + tid + FB);
    __syncthreads();

    const int q0 = qb + tid, q1 = q0 + FB;
    const float T0 = tmin_of(q0), T1 = tmin_of(q1);
    const float2 xa = ch1[q0];
    const float2 xb = ch1[q1];
    float2* p0 = &g_pair[(q0 * NSEG + sl) * SEG];
    float2* p1 = &g_pair[(q1 * NSEG + sl) * SEG];

    int c0 = 0, c1 = 0;
#pragma unroll 8
    for (int t = 0; t < SSLEN; ++t) {
        float4 c = sc[t];
        float s0 = s_of(c.x, c.y, c.z, xa.x, xa.y);
        float s1 = s_of(c.x, c.y, c.z, xb.x, xb.y);
        float fi = __int_as_float(sl * SSLEN + t);
        if (s0 >= T0) { p0[c0 & (SEG - 1)] = make_float2(s0, fi); ++c0; }
        if (s1 >= T1) { p1[c1 & (SEG - 1)] = make_float2(s1, fi); ++c1; }
    }
    g_cnt[q0][sl] = min(c0, SEG);
    g_cnt[q1][sl] = min(c1, SEG);
}

// ---------------------------------------------------------------------------
// Kernel 3 (R7-validated): warp-cooperative stable top-16. One warp per
// query; lane l owns segment l (mean 1.3 entries, ascending index order ->
// stable). 16 rounds of redux-max(key) + redux-min(idx) tie-break
// == (s desc, idx asc) == lax.top_k order.
// ---------------------------------------------------------------------------
__global__ __launch_bounds__(FB)
void select_kernel()
{
    const int j    = (blockIdx.x * FB + threadIdx.x) >> 5;
    const int lane = threadIdx.x & 31;

    const int cn = g_cnt[j][lane];
    const float2* sp = &g_pair[(j * NSEG + lane) * SEG];

    float l[KTOP];
    int   li[KTOP];
#pragma unroll
    for (int m = 0; m < KTOP; ++m) { l[m] = -CUDART_INF_F; li[m] = 0x7fffffff; }

    for (int c = 0; c < cn; ++c) {
        float2 pr = sp[c];
        float s  = pr.x;
        int   ci = __float_as_int(pr.y);
        if (s > l[KTOP - 1]) {
#pragma unroll
            for (int m = KTOP - 1; m >= 1; --m) {
                bool up   = s > l[m - 1];
                bool here = (!up) && (s > l[m]);
                float nd  = up ? l[m - 1]  : (here ? s  : l[m]);
                int   ni  = up ? li[m - 1] : (here ? ci : li[m]);
                l[m] = nd; li[m] = ni;
            }
            if (s > l[0]) { l[0] = s; li[0] = ci; }
        }
    }

    int out[KTOP];
#pragma unroll
    for (int k = 0; k < KTOP; ++k) {
        unsigned key = fkey(l[0]);
        unsigned mx  = __reduce_max_sync(0xffffffffu, key);
        unsigned cnd = (key == mx) ? (unsigned)li[0] : 0xffffffffu;
        unsigned win = __reduce_min_sync(0xffffffffu, cnd);
        out[k] = (int)win;
        bool pop = (key == mx) && ((unsigned)li[0] == win);
#pragma unroll
        for (int m = 0; m < KTOP - 1; ++m) {
            l[m]  = pop ? l[m + 1]  : l[m];
            li[m] = pop ? li[m + 1] : li[m];
        }
        if (pop) { l[KTOP - 1] = -CUDART_INF_F; li[KTOP - 1] = 0x7fffffff; }
    }

    if (lane == 0) {
#pragma unroll
        for (int k = 0; k < KTOP; ++k)
            g_idx[j * KTOP + k] = out[k];
    }
}

// ---------------------------------------------------------------------------
// Kernel 4 (REBUILT): one thread per query. Coalesced g_idx loads
// (consecutive q in consecutive lanes), 16-way MLP on the g_cand gathers,
// register accumulation in ascending k (reference order), __expf/__logf
// fast paths. Block tree-reduce -> 64 partials.
// flat m = k*N + q -> a = g_idx[m] (g_idx flat == idx.reshape(-1)), b = q.
// ---------------------------------------------------------------------------
__global__ __launch_bounds__(FB)
void reduce_kernel(const float2* __restrict__ ch1)
{
    const float scale = -0.5f / 2.25f;   // -0.5 / sigma2^2, sigma2 = 1.5
    const int tid = threadIdx.x;
    const int q   = blockIdx.x * FB + tid;

    int a[KTOP];
#pragma unroll
    for (int k = 0; k < KTOP; ++k)
        a[k] = g_idx[k * NQ + q];        // coalesced along q

    const float2 x = ch1[q];
    float esum = 0.0f;
#pragma unroll
    for (int k = 0; k < KTOP; ++k) {
        float4 c = g_cand[a[k]];
        float dy1 = x.x - c.x;
        float dy2 = x.y - c.y;
        esum += __expf(scale * __fmaf_rn(dy2, dy2, __fmul_rn(dy1, dy1)));
    }

    float expD = esum * (1.0f / (float)NQ);
    float v = (expD != 0.0f) ? __logf(expD) : 0.0f;

    __shared__ float red[FB];
    red[tid] = v;
    __syncthreads();
#pragma unroll
    for (int off = FB / 2; off > 0; off >>= 1) {
        if (tid < off) red[tid] += red[tid + off];
        __syncthreads();
    }
    if (tid == 0) g_part[blockIdx.x] = red[0];
}

// ---------------------------------------------------------------------------
// Kernel 5: deterministic tree-sum of 64 partials, negate, write out.
// ---------------------------------------------------------------------------
__global__ __launch_bounds__(64)
void final_kernel(float* __restrict__ out)
{
    __shared__ float red[64];
    red[threadIdx.x] = g_part[threadIdx.x];
    __syncthreads();
#pragma unroll
    for (int off = 32; off > 0; off >>= 1) {
        if (threadIdx.x < off) red[threadIdx.x] += red[threadIdx.x + off];
        __syncthreads();
    }
    if (threadIdx.x == 0) out[0] = -red[0];
}

// ---------------------------------------------------------------------------
extern "C" void kernel_launch(void* const* d_in, const int* in_sizes, int n_in,
                              void* d_out, int out_size)
{
    const float2* ch1 = (const float2*)d_in[0];
    const float2* ch2 = (const float2*)d_in[1];
    const float*  M1  = (const float*)d_in[2];
    const float*  M2  = (const float*)d_in[3];
    float* out = (float*)d_out;

    dim3 ggrid(NQ / (FB * QPT), NGRP * NSUB);   // (32, 32)
    gmax_kernel<<<ggrid, FB>>>(ch1, ch2, M1, M2);

    dim3 fgrid(NQ / (FB * QPT), NSEG);          // (32, 32)
    filter_kernel<<<fgrid, FB>>>(ch1, ch2, M1, M2);

    select_kernel<<<NQ * 32 / FB, FB>>>();      // 2048 blocks, 1 warp/query

    reduce_kernel<<<NRB, FB>>>(ch1);            // 64 blocks, 1 thread/query

    final_kernel<<<1, 64>>>(out);
}

// round 11
// speedup vs baseline: 1.1068x; 1.0050x over previous
#include <cuda_runtime.h>
#include <math_constants.h>

// Shapes fixed by setup_inputs: N=8192, K=16
#define NQ     8192
#define KTOP   16
#define NSEG   32                // filter sub-slices
#define SSLEN  256               // candidates per sub-slice
#define SEG    16                // per-(query,subslice) admitted cap (mean ~1.3)
#define NGRP   8                 // threshold groups (top-2 each -> >=16 admits)
#define NSUB   4                 // sub-partials per group
#define GSUB   96                // candidates per sub-partial (8*4*96 = 3072)
#define FB     128               // threads per block
#define QPT    2                 // queries per thread (gmax/filter)
#define RTB    256               // reduce threads per block
#define KSP    4                 // k-split per query (4 threads/query)
#define NRB    (NQ * KSP / RTB)  // 128 reduce blocks

// Static scratch (no runtime allocation allowed)
__device__ float4 g_cand[NQ];                  // (cx, cy, -0.5|c|^2, 0) for reduce
__device__ float2 g_gmax2[NGRP * NSUB][NQ];    // per-(group,sub) top-2 of s
__device__ float2 g_pair[NQ * NSEG * SEG];     // admitted (s, idx-bits)
__device__ int    g_cnt[NQ][NSEG];             // per-(query,subslice) counts
__device__ int    g_idx[NQ * KTOP];            // top-16 indices, query-major
__device__ float  g_part[NRB];                 // partial sums

// score: s = x.c - 0.5|c|^2  (dist = |x|^2 - 2s; larger s == closer).
// Explicit FMA chain -> bitwise identical in gmax and filter.
__device__ __forceinline__ float s_of(float cx, float cy, float nh,
                                      float x1, float x2)
{
    return __fmaf_rn(x2, cy, __fmaf_rn(x1, cx, nh));
}

// candidate prep: poly(ch2[i]) and -0.5*|.|^2, explicit FMA chain so every
// kernel computing it inline produces identical bits.
__device__ __forceinline__ float4 poly4(const float2* __restrict__ ch2,
                                        const float* __restrict__ M1,
                                        const float* __restrict__ M2, int i)
{
    float2 a = ch2[i];
    float p  = __fmul_rn(a.x, a.y);
    float y1 = __fmaf_rn(M1[1], a.y, __fmaf_rn(M1[2], a.x, __fmaf_rn(M1[3], p, M1[0])));
    float y2 = __fmaf_rn(M2[1], a.y, __fmaf_rn(M2[2], a.x, __fmaf_rn(M2[3], p, M2[0])));
    float nh = -0.5f * __fmaf_rn(y1, y1, __fmul_rn(y2, y2));
    return make_float4(y1, y2, nh, 0.0f);
}

// order-preserving float->uint key (monotone)
__device__ __forceinline__ unsigned fkey(float f)
{
    unsigned u = __float_as_uint(f);
    return u ^ ((unsigned)((int)u >> 31) | 0x80000000u);
}

// ---------------------------------------------------------------------------
// Kernel 1 (validated): gmax. Block = (256 queries via 2/thread,
// sub-partial y). y = g*4+sub covers candidates [y*96, y*96+96).
// Branch-free top-2 per query. y==0 blocks also write g_cand (fused prep).
// ---------------------------------------------------------------------------
__global__ __launch_bounds__(FB)
void gmax_kernel(const float2* __restrict__ ch1, const float2* __restrict__ ch2,
                 const float* __restrict__ M1, const float* __restrict__ M2)
{
    __shared__ float4 sc[GSUB];

    const int tid = threadIdx.x;
    const int y   = blockIdx.y;
    const int qb  = blockIdx.x * (FB * QPT);

    if (tid < GSUB)
        sc[tid] = poly4(ch2, M1, M2, y * GSUB + tid);

    if (y == 0) {   // fused prep for reduce's gather table
        int i0 = qb + tid;
        g_cand[i0]      = poly4(ch2, M1, M2, i0);
        g_cand[i0 + FB] = poly4(ch2, M1, M2, i0 + FB);
    }
    __syncthreads();

    const int q0 = qb + tid, q1 = q0 + FB;
    const float2 xa = ch1[q0];
    const float2 xb = ch1[q1];

    float m10 = -CUDART_INF_F, m20 = -CUDART_INF_F;
    float m11 = -CUDART_INF_F, m21 = -CUDART_INF_F;
#pragma unroll 8
    for (int t = 0; t < GSUB; ++t) {
        float4 c = sc[t];
        float s0 = s_of(c.x, c.y, c.z, xa.x, xa.y);
        float s1 = s_of(c.x, c.y, c.z, xb.x, xb.y);
        m20 = fmaxf(m20, fminf(m10, s0));  m10 = fmaxf(m10, s0);
        m21 = fmaxf(m21, fminf(m11, s1));  m11 = fmaxf(m11, s1);
    }
    g_gmax2[y][q0] = make_float2(m10, m20);
    g_gmax2[y][q1] = make_float2(m11, m21);
}

// exact top-2 merge of 4 sub-partials per group; T = min over groups of m2.
// Guarantee: every group's true top-2 have s >= m2 >= T  ->  >=16 admits.
__device__ __forceinline__ float tmin_of(int j)
{
    float T = CUDART_INF_F;
#pragma unroll
    for (int g = 0; g < NGRP; ++g) {
        float m1 = -CUDART_INF_F, m2 = -CUDART_INF_F;
#pragma unroll
        for (int sb = 0; sb < NSUB; ++sb) {
            float2 p = g_gmax2[g * NSUB + sb][j];
            m2 = fmaxf(fmaxf(m2, p.y), fminf(m1, p.x));
            m1 = fmaxf(m1, p.x);
        }
        T = fminf(T, m2);
    }
    return T;
}

// ---------------------------------------------------------------------------
// Kernel 2 (validated): filter (+tmin fused). Block = (256 queries via
// 2/thread, sub-slice sl). Appends (s, idx) with s >= T to private segments;
// register counters -> deterministic, ascending-index order (stable).
// ---------------------------------------------------------------------------
__global__ __launch_bounds__(FB)
void filter_kernel(const float2* __restrict__ ch1, const float2* __restrict__ ch2,
                   const float* __restrict__ M1, const float* __restrict__ M2)
{
    __shared__ float4 sc[SSLEN];   // 4 KB

    const int tid = threadIdx.x;
    const int sl  = blockIdx.y;
    const int qb  = blockIdx.x * (FB * QPT);

    sc[tid]      = poly4(ch2, M1, M2, sl * SSLEN + tid);
    sc[tid + FB] = poly4(ch2, M1, M2, sl * SSLEN + tid + FB);
    __syncthreads();

    const int q0 = qb + tid, q1 = q0 + FB;
    const float T0 = tmin_of(q0), T1 = tmin_of(q1);
    const float2 xa = ch1[q0];
    const float2 xb = ch1[q1];
    float2* p0 = &g_pair[(q0 * NSEG + sl) * SEG];
    float2* p1 = &g_pair[(q1 * NSEG + sl) * SEG];

    int c0 = 0, c1 = 0;
#pragma unroll 8
    for (int t = 0; t < SSLEN; ++t) {
        float4 c = sc[t];
        float s0 = s_of(c.x, c.y, c.z, xa.x, xa.y);
        float s1 = s_of(c.x, c.y, c.z, xb.x, xb.y);
        float fi = __int_as_float(sl * SSLEN + t);
        if (s0 >= T0) { p0[c0 & (SEG - 1)] = make_float2(s0, fi); ++c0; }
        if (s1 >= T1) { p1[c1 & (SEG - 1)] = make_float2(s1, fi); ++c1; }
    }
    g_cnt[q0][sl] = min(c0, SEG);
    g_cnt[q1][sl] = min(c1, SEG);
}

// ---------------------------------------------------------------------------
// Kernel 3 (validated): warp-cooperative stable top-16. One warp per
// query; lane l owns segment l (mean 1.3 entries, ascending index order ->
// stable). 16 rounds of redux-max(key) + redux-min(idx) tie-break
// == (s desc, idx asc) == lax.top_k order.
// ---------------------------------------------------------------------------
__global__ __launch_bounds__(FB)
void select_kernel()
{
    const int j    = (blockIdx.x * FB + threadIdx.x) >> 5;
    const int lane = threadIdx.x & 31;

    const int cn = g_cnt[j][lane];
    const float2* sp = &g_pair[(j * NSEG + lane) * SEG];

    float l[KTOP];
    int   li[KTOP];
#pragma unroll
    for (int m = 0; m < KTOP; ++m) { l[m] = -CUDART_INF_F; li[m] = 0x7fffffff; }

    for (int c = 0; c < cn; ++c) {
        float2 pr = sp[c];
        float s  = pr.x;
        int   ci = __float_as_int(pr.y);
        if (s > l[KTOP - 1]) {
#pragma unroll
            for (int m = KTOP - 1; m >= 1; --m) {
                bool up   = s > l[m - 1];
                bool here = (!up) && (s > l[m]);
                float nd  = up ? l[m - 1]  : (here ? s  : l[m]);
                int   ni  = up ? li[m - 1] : (here ? ci : li[m]);
                l[m] = nd; li[m] = ni;
            }
            if (s > l[0]) { l[0] = s; li[0] = ci; }
        }
    }

    int out[KTOP];
#pragma unroll
    for (int k = 0; k < KTOP; ++k) {
        unsigned key = fkey(l[0]);
        unsigned mx  = __reduce_max_sync(0xffffffffu, key);
        unsigned cnd = (key == mx) ? (unsigned)li[0] : 0xffffffffu;
        unsigned win = __reduce_min_sync(0xffffffffu, cnd);
        out[k] = (int)win;
        bool pop = (key == mx) && ((unsigned)li[0] == win);
#pragma unroll
        for (int m = 0; m < KTOP - 1; ++m) {
            l[m]  = pop ? l[m + 1]  : l[m];
            li[m] = pop ? li[m + 1] : li[m];
        }
        if (pop) { l[KTOP - 1] = -CUDART_INF_F; li[KTOP - 1] = 0x7fffffff; }
    }

    if (lane == 0) {
#pragma unroll
        for (int k = 0; k < KTOP; ++k)
            g_idx[j * KTOP + k] = out[k];
    }
}

// ---------------------------------------------------------------------------
// Kernel 4 (REWORKED): 4 threads per query (k-quad split). 1024 warps chip-
// wide (4x R10), MLP=4 gathers per thread, coalesced-in-q g_idx loads.
// Quad combine via 2 shfl steps (fixed order -> deterministic), leader does
// log, block tree-sums 64 query values -> 128 partials.
// flat m = k*N + q -> a = g_idx[m] (g_idx flat == idx.reshape(-1)), b = q.
// ---------------------------------------------------------------------------
__global__ __launch_bounds__(RTB)
void reduce_kernel(const float2* __restrict__ ch1)
{
    const float scale = -0.5f / 2.25f;   // -0.5 / sigma2^2, sigma2 = 1.5
    const int tid = threadIdx.x;
    const int gt  = blockIdx.x * RTB + tid;
    const int q   = gt >> 2;             // query
    const int kq  = gt & 3;              // k-quad: k in [4*kq, 4*kq+4)

    int a[4];
#pragma unroll
    for (int i = 0; i < 4; ++i)
        a[i] = g_idx[(kq * 4 + i) * NQ + q];

    const float2 x = ch1[q];
    float esum = 0.0f;
#pragma unroll
    for (int i = 0; i < 4; ++i) {
        float4 c = g_cand[a[i]];
        float dy1 = x.x - c.x;
        float dy2 = x.y - c.y;
        esum += __expf(scale * __fmaf_rn(dy2, dy2, __fmul_rn(dy1, dy1)));
    }

    // combine the 4 k-quads of this query (lanes 4b..4b+3), fixed order
    esum += __shfl_xor_sync(0xffffffffu, esum, 1);
    esum += __shfl_xor_sync(0xffffffffu, esum, 2);

    __shared__ float red[RTB / 4];
    if (kq == 0) {
        float expD = esum * (1.0f / (float)NQ);
        red[tid >> 2] = (expD != 0.0f) ? __logf(expD) : 0.0f;
    }
    __syncthreads();

    const int nq = RTB / 4;              // 64 query values
#pragma unroll
    for (int off = nq / 2; off > 0; off >>= 1) {
        if (tid < off) red[tid] += red[tid + off];
        __syncthreads();
    }
    if (tid == 0) g_part[blockIdx.x] = red[0];
}

// ---------------------------------------------------------------------------
// Kernel 5: deterministic tree-sum of 128 partials, negate, write out.
// ---------------------------------------------------------------------------
__global__ __launch_bounds__(NRB)
void final_kernel(float* __restrict__ out)
{
    __shared__ float red[NRB];
    red[threadIdx.x] = g_part[threadIdx.x];
    __syncthreads();
#pragma unroll
    for (int off = NRB / 2; off > 0; off >>= 1) {
        if (threadIdx.x < off) red[threadIdx.x] += red[threadIdx.x + off];
        __syncthreads();
    }
    if (threadIdx.x == 0) out[0] = -red[0];
}

// ---------------------------------------------------------------------------
extern "C" void kernel_launch(void* const* d_in, const int* in_sizes, int n_in,
                              void* d_out, int out_size)
{
    const float2* ch1 = (const float2*)d_in[0];
    const float2* ch2 = (const float2*)d_in[1];
    const float*  M1  = (const float*)d_in[2];
    const float*  M2  = (const float*)d_in[3];
    float* out = (float*)d_out;

    dim3 ggrid(NQ / (FB * QPT), NGRP * NSUB);   // (32, 32)
    gmax_kernel<<<ggrid, FB>>>(ch1, ch2, M1, M2);

    dim3 fgrid(NQ / (FB * QPT), NSEG);          // (32, 32)
    filter_kernel<<<fgrid, FB>>>(ch1, ch2, M1, M2);

    select_kernel<<<NQ * 32 / FB, FB>>>();      // 2048 blocks, 1 warp/query

    reduce_kernel<<<NRB, RTB>>>(ch1);           // 128 blocks, 4 threads/query

    final_kernel<<<1, NRB>>>(out);
}